// round 10
// baseline (speedup 1.0000x reference)
#include <cuda_runtime.h>
#include <cuda_fp16.h>
#include <math.h>
#include <stdint.h>

#define NN 10000
#define NE 160000
#define NB 10
#define RN 100
#define WN 704
#define NCH 11
#define EB 256        /* edges per CTA (two 128-edge subtiles) */
#define KG 128
#define HS 130        /* hh row stride in halves (conflict-free) */

#define SQ3    1.7320508075688772f
#define ISQ3   0.5773502691896258f
#define SQ75   2.7386127875258306f
#define C_SC   0.25f
#define C_V0   0.35355339059327373f
#define C_CG   0.20412414523193152f
#define I24    0.20412414523193152f
#define I32    0.17677669529663687f
#define I8     0.35355339059327373f
#define I16    0.25f
#define THIRD  0.3333333333333333f

__device__ float g_rbf[NE*NB];
__device__ float g_sh1[NE*3];
__device__ float g_s[NN*16];
__device__ float g_v[NN*24];
__device__ float g_aggs[NN*24];
__device__ float g_aggv[NN*128];     /* [N][32][4] for float4 atomics */
__device__ uint16_t g_bt[4*WN*KG];   /* fc_w^T fp16, [l][n][k] padded */
__device__ float g_rwT[4*RN*12];     /* radial w transposed: [l][r][10 w + bias + pad] */

/* ---- smem layout (bytes) ----
   UNION @0: hh (256*130*2 = 66560) overlaid with feat (256*77*4 = 78848)
   COL   @78848 (1024)
   B     @79872 (2 x 16384)                                              */
#define OFF_U    0
#define OFF_COL  78848
#define OFF_B    79872
#define SM_TOT   112640
#define FST 77

__device__ __forceinline__ uint32_t smem_u32(const void* p){
    uint32_t a; asm("{ .reg .u64 t; cvta.to.shared.u64 t, %1; cvt.u32.u64 %0, t; }":"=r"(a):"l"(p)); return a;
}
__device__ __forceinline__ void cpa16(uint32_t dst, const void* src){
    asm volatile("cp.async.ca.shared.global [%0], [%1], 16;"::"r"(dst),"l"(src):"memory");
}
__device__ __forceinline__ void cp_commit(){ asm volatile("cp.async.commit_group;":::"memory"); }
__device__ __forceinline__ void cp_wait0(){ asm volatile("cp.async.wait_group 0;":::"memory"); }
__device__ __forceinline__ void ldsm4(uint32_t* r, uint32_t a){
    asm volatile("ldmatrix.sync.aligned.m8n8.x4.shared.b16 {%0,%1,%2,%3}, [%4];"
        :"=r"(r[0]),"=r"(r[1]),"=r"(r[2]),"=r"(r[3]):"r"(a));
}
__device__ __forceinline__ void mma16816(float* d, const uint32_t* a, uint32_t b0, uint32_t b1){
    asm volatile("mma.sync.aligned.m16n8k16.row.col.f32.f16.f16.f32 "
        "{%0,%1,%2,%3}, {%4,%5,%6,%7}, {%8,%9}, {%0,%1,%2,%3};"
        : "+f"(d[0]),"+f"(d[1]),"+f"(d[2]),"+f"(d[3])
        : "r"(a[0]),"r"(a[1]),"r"(a[2]),"r"(a[3]),"r"(b0),"r"(b1));
}
__device__ __forceinline__ void red2(float* p, float a, float b){
    atomicAdd((float2*)p, make_float2(a,b));
}
__device__ __forceinline__ void red4(float* p, float a, float b, float c){
    atomicAdd((float4*)p, make_float4(a,b,c,0.f));
}

/* ---------------- geometry ---------------- */
__global__ void geom_kernel(const float* __restrict__ pos, const int* __restrict__ row, const int* __restrict__ col){
    int e = blockIdx.x*256 + threadIdx.x;
    if (e >= NE) return;
    int r = row[e], c = col[e];
    float vx = pos[3*r]-pos[3*c], vy = pos[3*r+1]-pos[3*c+1], vz = pos[3*r+2]-pos[3*c+2];
    float len = sqrtf(vx*vx+vy*vy+vz*vz+1e-12f);
    float inv = 1.0f/len;
    g_sh1[3*e]=SQ3*vx*inv; g_sh1[3*e+1]=SQ3*vy*inv; g_sh1[3*e+2]=SQ3*vz*inv;
    const float step = 10.0f/9.0f;
#pragma unroll
    for (int k=0;k<NB;k++){ float d = len - (float)k*step; g_rbf[e*NB+k] = expf(-0.405f*d*d); }
}

/* ---------------- init ---------------- */
__global__ void init_kernel(const float* __restrict__ x, const float* __restrict__ ew){
    int idx = blockIdx.x*blockDim.x + threadIdx.x;
    int nt = gridDim.x*blockDim.x;
    if (idx < NN*16){
        int n = idx>>4, t = idx&15;
        float a = 0.f;
#pragma unroll
        for (int k=0;k<8;k++) a += x[n*8+k]*ew[k*16+t];
        g_s[idx] = a*I8;
    }
    for (int i=idx;i<NN*24;i+=nt){ g_v[i]=0.f; g_aggs[i]=0.f; }
    for (int i=idx;i<NN*128;i+=nt) g_aggv[i]=0.f;
}

/* ---------------- one-time conversions ---------------- */
__global__ void conv_fcw(const float* __restrict__ fcw, const float* __restrict__ fcb){
    int idx = blockIdx.x*256 + threadIdx.x;
    if (idx >= 4*WN*KG) return;
    int k = idx & (KG-1);
    int n = (idx >> 7) % WN;
    int l = idx / (WN*KG);
    float v = 0.f;
    if (k < 100)       v = fcw[(size_t)(l*RN + k)*WN + n];
    else if (k == 100) v = fcb[l*WN + n];
    __half h = __float2half_rn(v);
    g_bt[idx] = *(uint16_t*)&h;
}
__global__ void conv_rwt(const float* __restrict__ rw, const float* __restrict__ rb){
    int idx = blockIdx.x*256 + threadIdx.x;
    if (idx >= 4*RN*12) return;
    int j = idx % 12;
    int r = (idx/12) % RN;
    int l = idx / (RN*12);
    float v = 0.f;
    if (j < 10)      v = rw[l*1000 + j*100 + r];
    else if (j == 10) v = rb[l*100 + r];
    g_rwT[idx] = v;
}

/* ---------------- fused HMMA message kernel (256-edge tiles, B-frag sharing) ---------------- */
__global__ void __launch_bounds__(256, 2)
msg_kernel(int l, const int* __restrict__ row, const int* __restrict__ col){
    extern __shared__ char smem[];
    uint32_t sbase = smem_u32(smem);
    int tid = threadIdx.x;
    int wid = tid>>5, lane = tid&31;
    int g = lane>>2, tig = lane&3;
    int mi = lane>>3, rowin = lane&7;
    int tq = tig*2;
    int e0 = blockIdx.x*EB;

    uint16_t* hh = (uint16_t*)(smem + OFF_U);
    float*    featf = (float*)(smem + OFF_U);
    int*      colsm = (int*)(smem + OFF_COL);

    /* stage B chunk 0 */
    {
        const uint16_t* src = g_bt + (size_t)l*WN*KG;
#pragma unroll
        for (int i=0;i<4;i++){
            int cid = tid + i*256;
            int n = cid>>4, j = cid&15;
            cpa16(sbase + OFF_B + ((n*16 + (j ^ (n&7)))<<4), src + (size_t)n*KG + j*8);
        }
        cp_commit();
    }

    /* h compute: thread = edge */
    {
        int eg = e0 + tid;
        float rbf[NB];
        const float2* rb2 = (const float2*)(g_rbf + (size_t)eg*NB);
#pragma unroll
        for (int i=0;i<5;i++){ float2 v = rb2[i]; rbf[i*2]=v.x; rbf[i*2+1]=v.y; }
        const float4* wt = (const float4*)(g_rwT + l*RN*12);
        uint16_t* hrow = hh + tid*HS;
#pragma unroll 4
        for (int r=0;r<RN;r++){
            float4 c0 = wt[r*3], c1 = wt[r*3+1], c2 = wt[r*3+2];
            float a = c2.z
                + rbf[0]*c0.x + rbf[1]*c0.y + rbf[2]*c0.z + rbf[3]*c0.w
                + rbf[4]*c1.x + rbf[5]*c1.y + rbf[6]*c1.z + rbf[7]*c1.w
                + rbf[8]*c2.x + rbf[9]*c2.y;
            a = fmaxf(a, 0.f);
            __half hv = __float2half_rn(a);
            hrow[r] = *(uint16_t*)&hv;
        }
        hrow[100] = 0x3C00;
#pragma unroll
        for (int r=101;r<112;r++) hrow[r] = 0;
    }
    __syncthreads();

    /* A fragment preload: subtile0 rows r0,r0+8 ; subtile1 rows 128+r0,+8 */
    uint32_t A0[28], A1[28];
    int r0 = wid*16 + g;
    {
#pragma unroll
        for (int ks=0;ks<7;ks++){
            int k0 = ks*16 + tq;
            A0[ks*4+0] = *(uint32_t*)&hh[r0*HS + k0];
            A0[ks*4+1] = *(uint32_t*)&hh[(r0+8)*HS + k0];
            A0[ks*4+2] = *(uint32_t*)&hh[r0*HS + k0+8];
            A0[ks*4+3] = *(uint32_t*)&hh[(r0+8)*HS + k0+8];
            A1[ks*4+0] = *(uint32_t*)&hh[(128+r0)*HS + k0];
            A1[ks*4+1] = *(uint32_t*)&hh[(136+r0)*HS + k0];
            A1[ks*4+2] = *(uint32_t*)&hh[(128+r0)*HS + k0+8];
            A1[ks*4+3] = *(uint32_t*)&hh[(136+r0)*HS + k0+8];
        }
    }
    __syncthreads();   /* hh dead; feat overlays */

    /* features + col: thread = edge */
    {
        int e = tid, eg = e0 + e;
        int rr = row[eg];
        colsm[e] = col[eg];
        float* F = featf + e*FST;
#pragma unroll
        for (int t=0;t<16;t++) F[t] = g_s[rr*16+t];
#pragma unroll
        for (int i=0;i<24;i++) F[16+i] = g_v[rr*24+i];
        float s1x = g_sh1[eg*3], s1y = g_sh1[eg*3+1], s1z = g_sh1[eg*3+2];
        F[72]=s1x; F[73]=s1y; F[74]=s1z;
        float ux=s1x*ISQ3, uy=s1y*ISQ3, uz=s1z*ISQ3;
#pragma unroll
        for (int u=0;u<8;u++){
            float vx=F[16+u*3], vy=F[17+u*3], vz=F[18+u*3];
            float dot = ux*vx+uy*vy+uz*vz;
            F[40+u] = SQ3*dot;
            F[48+u*3] = SQ75*(dot*ux - vx*THIRD);
            F[49+u*3] = SQ75*(dot*uy - vy*THIRD);
            F[50+u*3] = SQ75*(dot*uz - vz*THIRD);
        }
    }
    cp_wait0();
    __syncthreads();

    const float* Fp0 = featf + r0*FST;
    const float* Fp1 = featf + (r0+8)*FST;
    const float* Fp2 = featf + (128+r0)*FST;
    const float* Fp3 = featf + (136+r0)*FST;
    int cn0 = colsm[r0], cn1 = colsm[r0+8], cn2 = colsm[128+r0], cn3 = colsm[136+r0];
    float m0[16], m1[16];

#pragma unroll
    for (int c=0;c<NCH;c++){
        if (c+1 < NCH){
            const uint16_t* src = g_bt + ((size_t)l*WN + (c+1)*64)*KG;
            uint32_t db = sbase + OFF_B + ((c+1)&1)*16384;
#pragma unroll
            for (int i=0;i<4;i++){
                int cid = tid + i*256;
                int n = cid>>4, j = cid&15;
                cpa16(db + ((n*16 + (j ^ (n&7)))<<4), src + (size_t)n*KG + j*8);
            }
            cp_commit();
        }

        float a8[24];   /* c==8/10: 4 edges x 2 j x 3 dims */
        float a9[8];    /* c==9 */
        if (c >= 8){
#pragma unroll
            for (int i=0;i<24;i++) a8[i]=0.f;
#pragma unroll
            for (int i=0;i<8;i++)  a9[i]=0.f;
        }
        if (c == 0){
#pragma unroll
            for (int i=0;i<16;i++) m0[i]=0.f;
        }
        if (c == 4){
#pragma unroll
            for (int i=0;i<16;i++) m1[i]=0.f;
        }

        uint32_t bb = sbase + OFF_B + (c&1)*16384;
#pragma unroll
        for (int p=0;p<2;p++){
            /* GEMM half-pass: nf = p*4+nf', both subtiles share B-frags */
            float acc0[16], acc1[16];
#pragma unroll
            for (int i=0;i<16;i++){ acc0[i]=0.f; acc1[i]=0.f; }
#pragma unroll
            for (int q4=0;q4<4;q4++){
#pragma unroll
                for (int nf=0;nf<4;nf++){
                    int nfg = p*4 + nf;
                    uint32_t bm[4];
                    ldsm4(bm, bb + (((nfg*8 + rowin)*16 + ((q4*4+mi) ^ rowin)) << 4));
                    mma16816(acc0 + nf*4, A0 + (2*q4)*4, bm[0], bm[1]);
                    mma16816(acc1 + nf*4, A1 + (2*q4)*4, bm[0], bm[1]);
                    if (q4 < 3){
                        mma16816(acc0 + nf*4, A0 + (2*q4+1)*4, bm[2], bm[3]);
                        mma16816(acc1 + nf*4, A1 + (2*q4+1)*4, bm[2], bm[3]);
                    }
                }
            }
            /* consume pass */
            if (c < 4){
#pragma unroll
                for (int nf=0;nf<4;nf++){
                    int u = c*4 + p*2 + (nf>>1);
                    int sl = (nf&1)*2;
                    float s0 = Fp0[u], s1 = Fp1[u], s2 = Fp2[u], s3 = Fp3[u];
                    m0[sl+0]  += acc0[nf*4+0]*s0;  m0[sl+1]  += acc0[nf*4+1]*s0;
                    m0[4+sl]  += acc0[nf*4+2]*s1;  m0[5+sl]  += acc0[nf*4+3]*s1;
                    m0[8+sl]  += acc1[nf*4+0]*s2;  m0[9+sl]  += acc1[nf*4+1]*s2;
                    m0[12+sl] += acc1[nf*4+2]*s3;  m0[13+sl] += acc1[nf*4+3]*s3;
                }
            } else if (c < 8){
#pragma unroll
                for (int nf=0;nf<4;nf++){
                    int u = (c-4)*4 + p*2 + (nf>>1);
                    int sl = (nf&1)*2;
                    float s0 = Fp0[u], s1 = Fp1[u], s2 = Fp2[u], s3 = Fp3[u];
                    m1[sl+0]  += acc0[nf*4+0]*s0;  m1[sl+1]  += acc0[nf*4+1]*s0;
                    m1[4+sl]  += acc0[nf*4+2]*s1;  m1[5+sl]  += acc0[nf*4+3]*s1;
                    m1[8+sl]  += acc1[nf*4+0]*s2;  m1[9+sl]  += acc1[nf*4+1]*s2;
                    m1[12+sl] += acc1[nf*4+2]*s3;  m1[13+sl] += acc1[nf*4+3]*s3;
                }
            } else if (c == 9){
#pragma unroll
                for (int nf=0;nf<4;nf++){
                    int u = p*4 + nf;
                    a9[0] += acc0[nf*4+0]*Fp0[40+u];  a9[1] += acc0[nf*4+1]*Fp0[40+u];
                    a9[2] += acc0[nf*4+2]*Fp1[40+u];  a9[3] += acc0[nf*4+3]*Fp1[40+u];
                    a9[4] += acc1[nf*4+0]*Fp2[40+u];  a9[5] += acc1[nf*4+1]*Fp2[40+u];
                    a9[6] += acc1[nf*4+2]*Fp3[40+u];  a9[7] += acc1[nf*4+3]*Fp3[40+u];
                }
            } else {  /* c==8 or c==10 */
                int fb = (c==8) ? 16 : 48;
#pragma unroll
                for (int nf=0;nf<4;nf++){
                    int u = p*4 + nf;
#pragma unroll
                    for (int d=0;d<3;d++){
                        a8[0+d]  += acc0[nf*4+0]*Fp0[fb+u*3+d];
                        a8[3+d]  += acc0[nf*4+1]*Fp0[fb+u*3+d];
                        a8[6+d]  += acc0[nf*4+2]*Fp1[fb+u*3+d];
                        a8[9+d]  += acc0[nf*4+3]*Fp1[fb+u*3+d];
                        a8[12+d] += acc1[nf*4+0]*Fp2[fb+u*3+d];
                        a8[15+d] += acc1[nf*4+1]*Fp2[fb+u*3+d];
                        a8[18+d] += acc1[nf*4+2]*Fp3[fb+u*3+d];
                        a8[21+d] += acc1[nf*4+3]*Fp3[fb+u*3+d];
                    }
                }
            }
        }

        /* flushes */
        if (c == 3){
            red2(&g_aggs[cn0*24 + tq],     m0[0]*C_SC,  m0[1]*C_SC);
            red2(&g_aggs[cn0*24 + 8 + tq], m0[2]*C_SC,  m0[3]*C_SC);
            red2(&g_aggs[cn1*24 + tq],     m0[4]*C_SC,  m0[5]*C_SC);
            red2(&g_aggs[cn1*24 + 8 + tq], m0[6]*C_SC,  m0[7]*C_SC);
            red2(&g_aggs[cn2*24 + tq],     m0[8]*C_SC,  m0[9]*C_SC);
            red2(&g_aggs[cn2*24 + 8 + tq], m0[10]*C_SC, m0[11]*C_SC);
            red2(&g_aggs[cn3*24 + tq],     m0[12]*C_SC, m0[13]*C_SC);
            red2(&g_aggs[cn3*24 + 8 + tq], m0[14]*C_SC, m0[15]*C_SC);
        } else if (c == 7){
            const float* Fs[4] = {Fp0, Fp1, Fp2, Fp3};
            int cns[4] = {cn0, cn1, cn2, cn3};
#pragma unroll
            for (int E=0;E<4;E++){
#pragma unroll
                for (int s=0;s<4;s++){
                    int t = (s>>1)*8 + tq + (s&1);
                    float f = m1[E*4+s]*C_SC;
                    red4(&g_aggv[cns[E]*128 + t*4], f*Fs[E][72], f*Fs[E][73], f*Fs[E][74]);
                }
            }
        } else if (c == 8){
            int cns[4] = {cn0, cn1, cn2, cn3};
#pragma unroll
            for (int E=0;E<4;E++){
                red4(&g_aggv[cns[E]*128 + (16+tq)*4],   a8[E*6+0]*C_V0, a8[E*6+1]*C_V0, a8[E*6+2]*C_V0);
                red4(&g_aggv[cns[E]*128 + (16+tq+1)*4], a8[E*6+3]*C_V0, a8[E*6+4]*C_V0, a8[E*6+5]*C_V0);
            }
        } else if (c == 9){
            red2(&g_aggs[cn0*24 + 16 + tq], a9[0]*C_CG, a9[1]*C_CG);
            red2(&g_aggs[cn1*24 + 16 + tq], a9[2]*C_CG, a9[3]*C_CG);
            red2(&g_aggs[cn2*24 + 16 + tq], a9[4]*C_CG, a9[5]*C_CG);
            red2(&g_aggs[cn3*24 + 16 + tq], a9[6]*C_CG, a9[7]*C_CG);
        } else if (c == 10){
            int cns[4] = {cn0, cn1, cn2, cn3};
#pragma unroll
            for (int E=0;E<4;E++){
                red4(&g_aggv[cns[E]*128 + (24+tq)*4],   a8[E*6+0]*C_CG, a8[E*6+1]*C_CG, a8[E*6+2]*C_CG);
                red4(&g_aggv[cns[E]*128 + (24+tq+1)*4], a8[E*6+3]*C_CG, a8[E*6+4]*C_CG, a8[E*6+5]*C_CG);
            }
        }

        cp_wait0();
        __syncthreads();
    }
}

/* ---------------- node updates (zero folded in) ---------------- */
__global__ void upd_s(int l, const float* __restrict__ lws){
    int idx = blockIdx.x*256 + threadIdx.x;
    int n = idx>>4, t = idx&15;
    float a = 0.f;
#pragma unroll
    for (int u=0;u<24;u++) a += g_aggs[n*24+u]*lws[l*384+u*16+t];
    __syncthreads();
    g_s[idx] += a*I24;
    int base = (blockIdx.x<<4)*24;
    for (int i=threadIdx.x;i<384;i+=256) g_aggs[base+i] = 0.f;
}
__global__ void upd_v(int l, const float* __restrict__ lwv){
    int idx = blockIdx.x*256 + threadIdx.x;
    bool act = idx < NN*8;
    int n = act ? (idx>>3) : 0, w = idx&7;
    float ax=0.f, ay=0.f, az=0.f;
    if (act){
#pragma unroll
        for (int u=0;u<32;u++){
            float lw = lwv[l*256+u*8+w];
            ax += g_aggv[n*128+u*4+0]*lw;
            ay += g_aggv[n*128+u*4+1]*lw;
            az += g_aggv[n*128+u*4+2]*lw;
        }
    }
    __syncthreads();
    if (act){
        g_v[n*24+w*3+0] += ax*I32;
        g_v[n*24+w*3+1] += ay*I32;
        g_v[n*24+w*3+2] += az*I32;
    }
    int base = blockIdx.x*32*128;
    for (int i=threadIdx.x;i<4096;i+=256){
        int gidx = base+i;
        if (gidx < NN*128) g_aggv[gidx] = 0.f;
    }
}

/* ---------------- output ---------------- */
__global__ void out_kernel(const float* __restrict__ ow, float* __restrict__ out){
    int idx = blockIdx.x*256 + threadIdx.x;
    if (idx >= NN*8) return;
    int n = idx>>3, t = idx&7;
    float a = 0.f;
#pragma unroll
    for (int k=0;k<16;k++) a += g_s[n*16+k]*ow[k*8+t];
    out[idx] = a*I16;
}

/* ---------------- launch ---------------- */
extern "C" void kernel_launch(void* const* d_in, const int* in_sizes, int n_in,
                              void* d_out, int out_size){
    const float *x=0, *pos=0, *embed_w=0, *radial_w=0, *radial_b=0;
    const float *fc_w=0, *fc_b=0, *lin_ws=0, *lin_wv=0, *out_w=0;
    const int *ei=0;
    for (int i=0;i<n_in;i++){
        switch (in_sizes[i]){
            case 80000:  x=(const float*)d_in[i]; break;
            case 30000:  pos=(const float*)d_in[i]; break;
            case 4000:   radial_w=(const float*)d_in[i]; break;
            case 400:    radial_b=(const float*)d_in[i]; break;
            case 281600: fc_w=(const float*)d_in[i]; break;
            case 2816:   fc_b=(const float*)d_in[i]; break;
            case 1536:   lin_ws=(const float*)d_in[i]; break;
            case 1024:   lin_wv=(const float*)d_in[i]; break;
            case 320000: ei=(const int*)d_in[i]; break;
            case 128:
                if (!embed_w) embed_w=(const float*)d_in[i];
                else          out_w=(const float*)d_in[i];
                break;
        }
    }
    const int* row = ei;
    const int* col = ei + NE;
    float* out = (float*)d_out;

    cudaFuncSetAttribute(msg_kernel, cudaFuncAttributeMaxDynamicSharedMemorySize, SM_TOT);

    conv_fcw<<<(4*WN*KG + 255)/256, 256>>>(fc_w, fc_b);
    conv_rwt<<<(4*RN*12 + 255)/256, 256>>>(radial_w, radial_b);
    geom_kernel<<<(NE+255)/256, 256>>>(pos, row, col);
    init_kernel<<<(NN*16+255)/256, 256>>>(x, embed_w);

    for (int l=0;l<4;l++){
        msg_kernel<<<NE/EB, 256, SM_TOT>>>(l, row, col);
        upd_s<<<NN*16/256, 256>>>(l, lin_ws);
        upd_v<<<(NN*8+255)/256, 256>>>(l, lin_wv);
    }
    out_kernel<<<(NN*8+255)/256, 256>>>(out_w, out);
}

// round 11
// speedup vs baseline: 1.0577x; 1.0577x over previous
#include <cuda_runtime.h>
#include <cuda_fp16.h>
#include <math.h>
#include <stdint.h>

#define NN 10000
#define NE 160000
#define NB 10
#define RN 100
#define WN 704
#define NCH 11
#define EB 128
#define KG 128
#define HS 130        /* hh row stride in halves (conflict-free) */

#define SQ3    1.7320508075688772f
#define ISQ3   0.5773502691896258f
#define SQ75   2.7386127875258306f
#define C_SC   0.25f
#define C_V0   0.35355339059327373f
#define C_CG   0.20412414523193152f
#define I24    0.20412414523193152f
#define I32    0.17677669529663687f
#define I8     0.35355339059327373f
#define I16    0.25f
#define THIRD  0.3333333333333333f

__device__ float g_rbf[NE*NB];
__device__ float g_sh1[NE*3];
__device__ float g_s[NN*16];
__device__ float g_v[NN*24];
__device__ float g_aggs[NN*24];
__device__ float g_aggv[NN*128];     /* [N][32][4] for float4 atomics */
__device__ uint16_t g_bt[4*WN*KG];   /* fc_w^T fp16, [l][n][k] padded */
__device__ float g_rwT[4*RN*12];     /* radial w transposed: [l][r][10 w + bias + pad] */

/* ---- smem layout (bytes) ----
   UNION @0: hh (128*130*2 = 33280) overlaid with feat (128*77*4 = 39424)
   COL   @39424 (512)
   B     @39936 (2 x 16384)                                              */
#define OFF_U    0
#define OFF_COL  39424
#define OFF_B    39936
#define SM_TOT   72704
#define FST 77

__device__ __forceinline__ uint32_t smem_u32(const void* p){
    uint32_t a; asm("{ .reg .u64 t; cvta.to.shared.u64 t, %1; cvt.u32.u64 %0, t; }":"=r"(a):"l"(p)); return a;
}
__device__ __forceinline__ void cpa16(uint32_t dst, const void* src){
    asm volatile("cp.async.ca.shared.global [%0], [%1], 16;"::"r"(dst),"l"(src):"memory");
}
__device__ __forceinline__ void cp_commit(){ asm volatile("cp.async.commit_group;":::"memory"); }
__device__ __forceinline__ void cp_wait0(){ asm volatile("cp.async.wait_group 0;":::"memory"); }
__device__ __forceinline__ void ldsm4(uint32_t* r, uint32_t a){
    asm volatile("ldmatrix.sync.aligned.m8n8.x4.shared.b16 {%0,%1,%2,%3}, [%4];"
        :"=r"(r[0]),"=r"(r[1]),"=r"(r[2]),"=r"(r[3]):"r"(a));
}
__device__ __forceinline__ void mma16816(float* d, const uint32_t* a, uint32_t b0, uint32_t b1){
    asm volatile("mma.sync.aligned.m16n8k16.row.col.f32.f16.f16.f32 "
        "{%0,%1,%2,%3}, {%4,%5,%6,%7}, {%8,%9}, {%0,%1,%2,%3};"
        : "+f"(d[0]),"+f"(d[1]),"+f"(d[2]),"+f"(d[3])
        : "r"(a[0]),"r"(a[1]),"r"(a[2]),"r"(a[3]),"r"(b0),"r"(b1));
}
__device__ __forceinline__ void red2(float* p, float a, float b){
    atomicAdd((float2*)p, make_float2(a,b));
}
__device__ __forceinline__ void red4(float* p, float a, float b, float c){
    atomicAdd((float4*)p, make_float4(a,b,c,0.f));
}

/* ---------------- geometry ---------------- */
__global__ void geom_kernel(const float* __restrict__ pos, const int* __restrict__ row, const int* __restrict__ col){
    int e = blockIdx.x*256 + threadIdx.x;
    if (e >= NE) return;
    int r = row[e], c = col[e];
    float vx = pos[3*r]-pos[3*c], vy = pos[3*r+1]-pos[3*c+1], vz = pos[3*r+2]-pos[3*c+2];
    float len = sqrtf(vx*vx+vy*vy+vz*vz+1e-12f);
    float inv = 1.0f/len;
    g_sh1[3*e]=SQ3*vx*inv; g_sh1[3*e+1]=SQ3*vy*inv; g_sh1[3*e+2]=SQ3*vz*inv;
    const float step = 10.0f/9.0f;
#pragma unroll
    for (int k=0;k<NB;k++){ float d = len - (float)k*step; g_rbf[e*NB+k] = expf(-0.405f*d*d); }
}

/* ---------------- init ---------------- */
__global__ void init_kernel(const float* __restrict__ x, const float* __restrict__ ew){
    int idx = blockIdx.x*blockDim.x + threadIdx.x;
    int nt = gridDim.x*blockDim.x;
    if (idx < NN*16){
        int n = idx>>4, t = idx&15;
        float a = 0.f;
#pragma unroll
        for (int k=0;k<8;k++) a += x[n*8+k]*ew[k*16+t];
        g_s[idx] = a*I8;
    }
    for (int i=idx;i<NN*24;i+=nt){ g_v[i]=0.f; g_aggs[i]=0.f; }
    for (int i=idx;i<NN*128;i+=nt) g_aggv[i]=0.f;
}

/* ---------------- one-time conversions ---------------- */
__global__ void conv_fcw(const float* __restrict__ fcw, const float* __restrict__ fcb){
    int idx = blockIdx.x*256 + threadIdx.x;
    if (idx >= 4*WN*KG) return;
    int k = idx & (KG-1);
    int n = (idx >> 7) % WN;
    int l = idx / (WN*KG);
    float v = 0.f;
    if (k < 100)       v = fcw[(size_t)(l*RN + k)*WN + n];
    else if (k == 100) v = fcb[l*WN + n];
    __half h = __float2half_rn(v);
    g_bt[idx] = *(uint16_t*)&h;
}
__global__ void conv_rwt(const float* __restrict__ rw, const float* __restrict__ rb){
    int idx = blockIdx.x*256 + threadIdx.x;
    if (idx >= 4*RN*12) return;
    int j = idx % 12;
    int r = (idx/12) % RN;
    int l = idx / (RN*12);
    float v = 0.f;
    if (j < 10)       v = rw[l*1000 + j*100 + r];
    else if (j == 10) v = rb[l*100 + r];
    g_rwT[idx] = v;
}

/* ---------------- fused HMMA message kernel ---------------- */
__global__ void __launch_bounds__(256, 2)
msg_kernel(int l, const int* __restrict__ row, const int* __restrict__ col){
    extern __shared__ char smem[];
    uint32_t sbase = smem_u32(smem);
    int tid = threadIdx.x;
    int wid = tid>>5, lane = tid&31;
    int g = lane>>2, tig = lane&3;
    int mi = lane>>3, rowin = lane&7;
    int tq = tig*2;
    int e0 = blockIdx.x*EB;

    uint16_t* hh = (uint16_t*)(smem + OFF_U);
    float*    featf = (float*)(smem + OFF_U);
    int*      colsm = (int*)(smem + OFF_COL);

    /* stage B chunk 0 */
    {
        const uint16_t* src = g_bt + (size_t)l*WN*KG;
#pragma unroll
        for (int i=0;i<4;i++){
            int cid = tid + i*256;
            int n = cid>>4, j = cid&15;
            cpa16(sbase + OFF_B + ((n*16 + (j ^ (n&7)))<<4), src + (size_t)n*KG + j*8);
        }
        cp_commit();
    }

    /* h compute: thread = (edge, half), broadcast float4 LDG weights */
    {
        int e = tid>>1, half = tid&1, eg = e0 + e;
        float rbf[NB];
        const float2* rb2 = (const float2*)(g_rbf + (size_t)eg*NB);
#pragma unroll
        for (int i=0;i<5;i++){ float2 v = rb2[i]; rbf[i*2]=v.x; rbf[i*2+1]=v.y; }
        const float4* wt = (const float4*)(g_rwT + l*RN*12);
        uint16_t* hrow = hh + e*HS;
        int r0h = half*50;
#pragma unroll 5
        for (int r=r0h; r<r0h+50; r++){
            float4 c0 = wt[r*3], c1 = wt[r*3+1], c2 = wt[r*3+2];
            float a = c2.z
                + rbf[0]*c0.x + rbf[1]*c0.y + rbf[2]*c0.z + rbf[3]*c0.w
                + rbf[4]*c1.x + rbf[5]*c1.y + rbf[6]*c1.z + rbf[7]*c1.w
                + rbf[8]*c2.x + rbf[9]*c2.y;
            a = fmaxf(a, 0.f);
            __half hv = __float2half_rn(a);
            hrow[r] = *(uint16_t*)&hv;
        }
        if (half == 0){
            hrow[100] = 0x3C00;                 /* bias row: A = 1.0 */
        } else {
#pragma unroll
            for (int r=101;r<112;r++) hrow[r] = 0;
        }
    }
    __syncthreads();

    /* A fragment preload for strip wid: rows r0, r0+8 */
    uint32_t ahh[28];
    int r0 = wid*16 + g;
    {
#pragma unroll
        for (int ks=0;ks<7;ks++){
            int k0 = ks*16 + tq;
            ahh[ks*4+0] = *(uint32_t*)&hh[r0*HS + k0];
            ahh[ks*4+1] = *(uint32_t*)&hh[(r0+8)*HS + k0];
            ahh[ks*4+2] = *(uint32_t*)&hh[r0*HS + k0+8];
            ahh[ks*4+3] = *(uint32_t*)&hh[(r0+8)*HS + k0+8];
        }
    }
    __syncthreads();   /* hh dead; feat overlays */

    /* features + col (thread = edge for tid<128) */
    if (tid < EB){
        int e = tid, eg = e0 + e;
        int rr = row[eg];
        colsm[e] = col[eg];
        float* F = featf + e*FST;
#pragma unroll
        for (int t=0;t<16;t++) F[t] = g_s[rr*16+t];
#pragma unroll
        for (int i=0;i<24;i++) F[16+i] = g_v[rr*24+i];
        float s1x = g_sh1[eg*3], s1y = g_sh1[eg*3+1], s1z = g_sh1[eg*3+2];
        F[72]=s1x; F[73]=s1y; F[74]=s1z;
        float ux=s1x*ISQ3, uy=s1y*ISQ3, uz=s1z*ISQ3;
#pragma unroll
        for (int u=0;u<8;u++){
            float vx=F[16+u*3], vy=F[17+u*3], vz=F[18+u*3];
            float dot = ux*vx+uy*vy+uz*vz;
            F[40+u] = SQ3*dot;
            F[48+u*3] = SQ75*(dot*ux - vx*THIRD);
            F[49+u*3] = SQ75*(dot*uy - vy*THIRD);
            F[50+u*3] = SQ75*(dot*uz - vz*THIRD);
        }
    }
    cp_wait0();
    __syncthreads();

    const float* F0 = featf + r0*FST;
    const float* F1 = featf + (r0+8)*FST;
    int cn0 = colsm[r0], cn1 = colsm[r0+8];
    float m0a[4], m0b[4], m1a[4], m1b[4];

#pragma unroll
    for (int c=0;c<NCH;c++){
        if (c+1 < NCH){
            const uint16_t* src = g_bt + ((size_t)l*WN + (c+1)*64)*KG;
            uint32_t db = sbase + OFF_B + ((c+1)&1)*16384;
#pragma unroll
            for (int i=0;i<4;i++){
                int cid = tid + i*256;
                int n = cid>>4, j = cid&15;
                cpa16(db + ((n*16 + (j ^ (n&7)))<<4), src + (size_t)n*KG + j*8);
            }
            cp_commit();
        }

        /* GEMM: 8 nf x 7 ksteps, single fp16 pass */
        float accf[32];
#pragma unroll
        for (int i=0;i<32;i++) accf[i] = 0.f;
        {
            uint32_t bb = sbase + OFF_B + (c&1)*16384;
#pragma unroll
            for (int q4=0;q4<4;q4++){
#pragma unroll
                for (int nf=0;nf<8;nf++){
                    uint32_t bm[4];
                    ldsm4(bm, bb + (((nf*8 + rowin)*16 + ((q4*4+mi) ^ rowin)) << 4));
                    mma16816(accf + nf*4, ahh + (2*q4)*4, bm[0], bm[1]);
                    if (q4 < 3)
                        mma16816(accf + nf*4, ahh + (2*q4+1)*4, bm[2], bm[3]);
                }
            }
        }

        /* messages from register accumulators (vector atomics) */
        if (c < 4){
            if (c == 0){
#pragma unroll
                for (int s=0;s<4;s++){ m0a[s]=0.f; m0b[s]=0.f; }
            }
#pragma unroll
            for (int nf=0;nf<8;nf++){
                float s0 = F0[c*4 + (nf>>1)];
                float s1 = F1[c*4 + (nf>>1)];
                int sl = (nf&1)*2;
                m0a[sl+0] += accf[nf*4+0]*s0;
                m0a[sl+1] += accf[nf*4+1]*s0;
                m0b[sl+0] += accf[nf*4+2]*s1;
                m0b[sl+1] += accf[nf*4+3]*s1;
            }
            if (c == 3){
                red2(&g_aggs[cn0*24 + tq],     m0a[0]*C_SC, m0a[1]*C_SC);
                red2(&g_aggs[cn0*24 + 8 + tq], m0a[2]*C_SC, m0a[3]*C_SC);
                red2(&g_aggs[cn1*24 + tq],     m0b[0]*C_SC, m0b[1]*C_SC);
                red2(&g_aggs[cn1*24 + 8 + tq], m0b[2]*C_SC, m0b[3]*C_SC);
            }
        } else if (c < 8){
            if (c == 4){
#pragma unroll
                for (int s=0;s<4;s++){ m1a[s]=0.f; m1b[s]=0.f; }
            }
#pragma unroll
            for (int nf=0;nf<8;nf++){
                float s0 = F0[(c-4)*4 + (nf>>1)];
                float s1 = F1[(c-4)*4 + (nf>>1)];
                int sl = (nf&1)*2;
                m1a[sl+0] += accf[nf*4+0]*s0;
                m1a[sl+1] += accf[nf*4+1]*s0;
                m1b[sl+0] += accf[nf*4+2]*s1;
                m1b[sl+1] += accf[nf*4+3]*s1;
            }
            if (c == 7){
#pragma unroll
                for (int s=0;s<4;s++){
                    int t = (s>>1)*8 + tq + (s&1);
                    float fa = m1a[s]*C_SC, fb = m1b[s]*C_SC;
                    red4(&g_aggv[cn0*128 + t*4], fa*F0[72], fa*F0[73], fa*F0[74]);
                    red4(&g_aggv[cn1*128 + t*4], fb*F1[72], fb*F1[73], fb*F1[74]);
                }
            }
        } else if (c == 8){
#pragma unroll
            for (int p=0;p<2;p++){
                int j = tq + p;
                float ax0=0.f,ay0=0.f,az0=0.f, ax1=0.f,ay1=0.f,az1=0.f;
#pragma unroll
                for (int nf=0;nf<8;nf++){
                    float w0 = accf[nf*4+p],  w1 = accf[nf*4+2+p];
                    ax0 += w0*F0[16+nf*3]; ay0 += w0*F0[17+nf*3]; az0 += w0*F0[18+nf*3];
                    ax1 += w1*F1[16+nf*3]; ay1 += w1*F1[17+nf*3]; az1 += w1*F1[18+nf*3];
                }
                red4(&g_aggv[cn0*128 + (16+j)*4], ax0*C_V0, ay0*C_V0, az0*C_V0);
                red4(&g_aggv[cn1*128 + (16+j)*4], ax1*C_V0, ay1*C_V0, az1*C_V0);
            }
        } else if (c == 9){
            float a0=0.f, a1=0.f, b0=0.f, b1=0.f;
#pragma unroll
            for (int nf=0;nf<8;nf++){
                a0 += accf[nf*4+0]*F0[40+nf];
                a1 += accf[nf*4+1]*F0[40+nf];
                b0 += accf[nf*4+2]*F1[40+nf];
                b1 += accf[nf*4+3]*F1[40+nf];
            }
            red2(&g_aggs[cn0*24 + 16 + tq], a0*C_CG, a1*C_CG);
            red2(&g_aggs[cn1*24 + 16 + tq], b0*C_CG, b1*C_CG);
        } else {
#pragma unroll
            for (int p=0;p<2;p++){
                int j = tq + p;
                float ax0=0.f,ay0=0.f,az0=0.f, ax1=0.f,ay1=0.f,az1=0.f;
#pragma unroll
                for (int nf=0;nf<8;nf++){
                    float w0 = accf[nf*4+p],  w1 = accf[nf*4+2+p];
                    ax0 += w0*F0[48+nf*3]; ay0 += w0*F0[49+nf*3]; az0 += w0*F0[50+nf*3];
                    ax1 += w1*F1[48+nf*3]; ay1 += w1*F1[49+nf*3]; az1 += w1*F1[50+nf*3];
                }
                red4(&g_aggv[cn0*128 + (24+j)*4], ax0*C_CG, ay0*C_CG, az0*C_CG);
                red4(&g_aggv[cn1*128 + (24+j)*4], ax1*C_CG, ay1*C_CG, az1*C_CG);
            }
        }

        cp_wait0();
        __syncthreads();
    }
}

/* ---------------- node updates (zero folded in) ---------------- */
__global__ void upd_s(int l, const float* __restrict__ lws){
    int idx = blockIdx.x*256 + threadIdx.x;
    int n = idx>>4, t = idx&15;
    float a = 0.f;
#pragma unroll
    for (int u=0;u<24;u++) a += g_aggs[n*24+u]*lws[l*384+u*16+t];
    __syncthreads();
    g_s[idx] += a*I24;
    int base = (blockIdx.x<<4)*24;
    for (int i=threadIdx.x;i<384;i+=256) g_aggs[base+i] = 0.f;
}
__global__ void upd_v(int l, const float* __restrict__ lwv){
    int idx = blockIdx.x*256 + threadIdx.x;
    bool act = idx < NN*8;
    int n = act ? (idx>>3) : 0, w = idx&7;
    float ax=0.f, ay=0.f, az=0.f;
    if (act){
#pragma unroll
        for (int u=0;u<32;u++){
            float lw = lwv[l*256+u*8+w];
            ax += g_aggv[n*128+u*4+0]*lw;
            ay += g_aggv[n*128+u*4+1]*lw;
            az += g_aggv[n*128+u*4+2]*lw;
        }
    }
    __syncthreads();
    if (act){
        g_v[n*24+w*3+0] += ax*I32;
        g_v[n*24+w*3+1] += ay*I32;
        g_v[n*24+w*3+2] += az*I32;
    }
    int base = blockIdx.x*32*128;
    for (int i=threadIdx.x;i<4096;i+=256){
        int gidx = base+i;
        if (gidx < NN*128) g_aggv[gidx] = 0.f;
    }
}

/* ---------------- output ---------------- */
__global__ void out_kernel(const float* __restrict__ ow, float* __restrict__ out){
    int idx = blockIdx.x*256 + threadIdx.x;
    if (idx >= NN*8) return;
    int n = idx>>3, t = idx&7;
    float a = 0.f;
#pragma unroll
    for (int k=0;k<16;k++) a += g_s[n*16+k]*ow[k*8+t];
    out[idx] = a*I16;
}

/* ---------------- launch ---------------- */
extern "C" void kernel_launch(void* const* d_in, const int* in_sizes, int n_in,
                              void* d_out, int out_size){
    const float *x=0, *pos=0, *embed_w=0, *radial_w=0, *radial_b=0;
    const float *fc_w=0, *fc_b=0, *lin_ws=0, *lin_wv=0, *out_w=0;
    const int *ei=0;
    for (int i=0;i<n_in;i++){
        switch (in_sizes[i]){
            case 80000:  x=(const float*)d_in[i]; break;
            case 30000:  pos=(const float*)d_in[i]; break;
            case 4000:   radial_w=(const float*)d_in[i]; break;
            case 400:    radial_b=(const float*)d_in[i]; break;
            case 281600: fc_w=(const float*)d_in[i]; break;
            case 2816:   fc_b=(const float*)d_in[i]; break;
            case 1536:   lin_ws=(const float*)d_in[i]; break;
            case 1024:   lin_wv=(const float*)d_in[i]; break;
            case 320000: ei=(const int*)d_in[i]; break;
            case 128:
                if (!embed_w) embed_w=(const float*)d_in[i];
                else          out_w=(const float*)d_in[i];
                break;
        }
    }
    const int* row = ei;
    const int* col = ei + NE;
    float* out = (float*)d_out;

    cudaFuncSetAttribute(msg_kernel, cudaFuncAttributeMaxDynamicSharedMemorySize, SM_TOT);

    conv_fcw<<<(4*WN*KG + 255)/256, 256>>>(fc_w, fc_b);
    conv_rwt<<<(4*RN*12 + 255)/256, 256>>>(radial_w, radial_b);
    geom_kernel<<<(NE+255)/256, 256>>>(pos, row, col);
    init_kernel<<<(NN*16+255)/256, 256>>>(x, embed_w);

    for (int l=0;l<4;l++){
        msg_kernel<<<NE/EB, 256, SM_TOT>>>(l, row, col);
        upd_s<<<NN*16/256, 256>>>(l, lin_ws);
        upd_v<<<(NN*8+255)/256, 256>>>(l, lin_wv);
    }
    out_kernel<<<(NN*8+255)/256, 256>>>(out_w, out);
}

// round 12
// speedup vs baseline: 1.1977x; 1.1324x over previous
#include <cuda_runtime.h>
#include <cuda_fp16.h>
#include <math.h>
#include <stdint.h>

#define NN 10000
#define NE 160000
#define NB 10
#define RN 100
#define WN 704
#define NCH 11
#define EB 128
#define KG 128
#define HS 130        /* hh row stride in halves (conflict-free) */

#define SQ3    1.7320508075688772f
#define ISQ3   0.5773502691896258f
#define SQ75   2.7386127875258306f
#define C_SC   0.25f
#define C_V0   0.35355339059327373f
#define C_CG   0.20412414523193152f
#define I24    0.20412414523193152f
#define I32    0.17677669529663687f
#define I8     0.35355339059327373f
#define I16    0.25f
#define THIRD  0.3333333333333333f

__device__ float g_rbf[NE*NB];
__device__ float g_sh1[NE*3];
__device__ float g_s[NN*16];
__device__ float g_v[NN*24];
__device__ float g_aggs[NN*24];
__device__ float g_aggv[NN*128];     /* [N][32][4] for float4 atomics */
__device__ uint16_t g_bt[4*WN*KG];   /* fc_w^T fp16, [l][n][k] padded */
__device__ float g_rwT[4*RN*12];     /* radial w transposed: [l][r][10 w + bias + pad] */

/* ---- smem layout (bytes) ----
   UNION @0: hh (128*130*2 = 33280) overlaid with feat (128*77*4 = 39424)
   COL   @39424 (512)
   B     @39936 (2 x 16384)                                              */
#define OFF_U    0
#define OFF_COL  39424
#define OFF_B    39936
#define SM_TOT   72704
#define FST 77

__device__ __forceinline__ uint32_t smem_u32(const void* p){
    uint32_t a; asm("{ .reg .u64 t; cvta.to.shared.u64 t, %1; cvt.u32.u64 %0, t; }":"=r"(a):"l"(p)); return a;
}
__device__ __forceinline__ void cpa16(uint32_t dst, const void* src){
    asm volatile("cp.async.ca.shared.global [%0], [%1], 16;"::"r"(dst),"l"(src):"memory");
}
__device__ __forceinline__ void cp_commit(){ asm volatile("cp.async.commit_group;":::"memory"); }
__device__ __forceinline__ void cp_wait0(){ asm volatile("cp.async.wait_group 0;":::"memory"); }
__device__ __forceinline__ void ldsm4(uint32_t* r, uint32_t a){
    asm volatile("ldmatrix.sync.aligned.m8n8.x4.shared.b16 {%0,%1,%2,%3}, [%4];"
        :"=r"(r[0]),"=r"(r[1]),"=r"(r[2]),"=r"(r[3]):"r"(a));
}
__device__ __forceinline__ void mma16816(float* d, const uint32_t* a, uint32_t b0, uint32_t b1){
    asm volatile("mma.sync.aligned.m16n8k16.row.col.f32.f16.f16.f32 "
        "{%0,%1,%2,%3}, {%4,%5,%6,%7}, {%8,%9}, {%0,%1,%2,%3};"
        : "+f"(d[0]),"+f"(d[1]),"+f"(d[2]),"+f"(d[3])
        : "r"(a[0]),"r"(a[1]),"r"(a[2]),"r"(a[3]),"r"(b0),"r"(b1));
}
__device__ __forceinline__ void red2(float* p, float a, float b){
    atomicAdd((float2*)p, make_float2(a,b));
}
__device__ __forceinline__ void red4(float* p, float a, float b, float c){
    atomicAdd((float4*)p, make_float4(a,b,c,0.f));
}

/* ---------------- geometry ---------------- */
__global__ void geom_kernel(const float* __restrict__ pos, const int* __restrict__ row, const int* __restrict__ col){
    int e = blockIdx.x*256 + threadIdx.x;
    if (e >= NE) return;
    int r = row[e], c = col[e];
    float vx = pos[3*r]-pos[3*c], vy = pos[3*r+1]-pos[3*c+1], vz = pos[3*r+2]-pos[3*c+2];
    float len = sqrtf(vx*vx+vy*vy+vz*vz+1e-12f);
    float inv = 1.0f/len;
    g_sh1[3*e]=SQ3*vx*inv; g_sh1[3*e+1]=SQ3*vy*inv; g_sh1[3*e+2]=SQ3*vz*inv;
    const float step = 10.0f/9.0f;
#pragma unroll
    for (int k=0;k<NB;k++){ float d = len - (float)k*step; g_rbf[e*NB+k] = expf(-0.405f*d*d); }
}

/* ---------------- init ---------------- */
__global__ void init_kernel(const float* __restrict__ x, const float* __restrict__ ew){
    int idx = blockIdx.x*blockDim.x + threadIdx.x;
    int nt = gridDim.x*blockDim.x;
    if (idx < NN*16){
        int n = idx>>4, t = idx&15;
        float a = 0.f;
#pragma unroll
        for (int k=0;k<8;k++) a += x[n*8+k]*ew[k*16+t];
        g_s[idx] = a*I8;
    }
    for (int i=idx;i<NN*24;i+=nt){ g_v[i]=0.f; g_aggs[i]=0.f; }
    for (int i=idx;i<NN*128;i+=nt) g_aggv[i]=0.f;
}

/* ---------------- one-time conversions ---------------- */
__global__ void conv_fcw(const float* __restrict__ fcw, const float* __restrict__ fcb){
    int idx = blockIdx.x*256 + threadIdx.x;
    if (idx >= 4*WN*KG) return;
    int k = idx & (KG-1);
    int n = (idx >> 7) % WN;
    int l = idx / (WN*KG);
    float v = 0.f;
    if (k < 100)       v = fcw[(size_t)(l*RN + k)*WN + n];
    else if (k == 100) v = fcb[l*WN + n];
    __half h = __float2half_rn(v);
    g_bt[idx] = *(uint16_t*)&h;
}
__global__ void conv_rwt(const float* __restrict__ rw, const float* __restrict__ rb){
    int idx = blockIdx.x*256 + threadIdx.x;
    if (idx >= 4*RN*12) return;
    int j = idx % 12;
    int r = (idx/12) % RN;
    int l = idx / (RN*12);
    float v = 0.f;
    if (j < 10)       v = rw[l*1000 + j*100 + r];
    else if (j == 10) v = rb[l*100 + r];
    g_rwT[idx] = v;
}

/* ---------------- fused HMMA message kernel: 4 warps, Tm=32 ---------------- */
__global__ void __launch_bounds__(128, 3)
msg_kernel(int l, const int* __restrict__ row, const int* __restrict__ col){
    extern __shared__ char smem[];
    uint32_t sbase = smem_u32(smem);
    int tid = threadIdx.x;
    int wid = tid>>5, lane = tid&31;
    int g = lane>>2, tig = lane&3;
    int mi = lane>>3, rowin = lane&7;
    int tq = tig*2;
    int e0 = blockIdx.x*EB;

    uint16_t* hh = (uint16_t*)(smem + OFF_U);
    float*    featf = (float*)(smem + OFF_U);
    int*      colsm = (int*)(smem + OFF_COL);

    /* stage B chunk 0 (1024 x 16B, 128 threads) */
    {
        const uint16_t* src = g_bt + (size_t)l*WN*KG;
#pragma unroll
        for (int i=0;i<8;i++){
            int cid = tid + i*128;
            int n = cid>>4, j = cid&15;
            cpa16(sbase + OFF_B + ((n*16 + (j ^ (n&7)))<<4), src + (size_t)n*KG + j*8);
        }
        cp_commit();
    }

    /* h compute: thread = edge, broadcast float4 LDG weights */
    {
        int eg = e0 + tid;
        float rbf[NB];
        const float2* rb2 = (const float2*)(g_rbf + (size_t)eg*NB);
#pragma unroll
        for (int i=0;i<5;i++){ float2 v = rb2[i]; rbf[i*2]=v.x; rbf[i*2+1]=v.y; }
        const float4* wt = (const float4*)(g_rwT + l*RN*12);
        uint16_t* hrow = hh + tid*HS;
#pragma unroll 4
        for (int r=0;r<RN;r++){
            float4 c0 = wt[r*3], c1 = wt[r*3+1], c2 = wt[r*3+2];
            float a = c2.z
                + rbf[0]*c0.x + rbf[1]*c0.y + rbf[2]*c0.z + rbf[3]*c0.w
                + rbf[4]*c1.x + rbf[5]*c1.y + rbf[6]*c1.z + rbf[7]*c1.w
                + rbf[8]*c2.x + rbf[9]*c2.y;
            a = fmaxf(a, 0.f);
            __half hv = __float2half_rn(a);
            hrow[r] = *(uint16_t*)&hv;
        }
        hrow[100] = 0x3C00;                 /* bias row: A = 1.0 */
#pragma unroll
        for (int r=101;r<112;r++) hrow[r] = 0;
    }
    __syncthreads();

    /* A fragment preload: warp strip = 32 edges (rows r0,+8 and r0+16,+24) */
    uint32_t A0[28], A1[28];
    int r0 = wid*32 + g;
    {
#pragma unroll
        for (int ks=0;ks<7;ks++){
            int k0 = ks*16 + tq;
            A0[ks*4+0] = *(uint32_t*)&hh[r0*HS + k0];
            A0[ks*4+1] = *(uint32_t*)&hh[(r0+8)*HS + k0];
            A0[ks*4+2] = *(uint32_t*)&hh[r0*HS + k0+8];
            A0[ks*4+3] = *(uint32_t*)&hh[(r0+8)*HS + k0+8];
            A1[ks*4+0] = *(uint32_t*)&hh[(r0+16)*HS + k0];
            A1[ks*4+1] = *(uint32_t*)&hh[(r0+24)*HS + k0];
            A1[ks*4+2] = *(uint32_t*)&hh[(r0+16)*HS + k0+8];
            A1[ks*4+3] = *(uint32_t*)&hh[(r0+24)*HS + k0+8];
        }
    }
    __syncthreads();   /* hh dead; feat overlays */

    /* features + col: thread = edge */
    {
        int e = tid, eg = e0 + e;
        int rr = row[eg];
        colsm[e] = col[eg];
        float* F = featf + e*FST;
#pragma unroll
        for (int t=0;t<16;t++) F[t] = g_s[rr*16+t];
#pragma unroll
        for (int i=0;i<24;i++) F[16+i] = g_v[rr*24+i];
        float s1x = g_sh1[eg*3], s1y = g_sh1[eg*3+1], s1z = g_sh1[eg*3+2];
        F[72]=s1x; F[73]=s1y; F[74]=s1z;
        float ux=s1x*ISQ3, uy=s1y*ISQ3, uz=s1z*ISQ3;
#pragma unroll
        for (int u=0;u<8;u++){
            float vx=F[16+u*3], vy=F[17+u*3], vz=F[18+u*3];
            float dot = ux*vx+uy*vy+uz*vz;
            F[40+u] = SQ3*dot;
            F[48+u*3] = SQ75*(dot*ux - vx*THIRD);
            F[49+u*3] = SQ75*(dot*uy - vy*THIRD);
            F[50+u*3] = SQ75*(dot*uz - vz*THIRD);
        }
    }
    cp_wait0();
    __syncthreads();

    const float* Fp0 = featf + r0*FST;
    const float* Fp1 = featf + (r0+8)*FST;
    const float* Fp2 = featf + (r0+16)*FST;
    const float* Fp3 = featf + (r0+24)*FST;
    int cn0 = colsm[r0], cn1 = colsm[r0+8], cn2 = colsm[r0+16], cn3 = colsm[r0+24];
    float m0[16], m1[16];

#pragma unroll
    for (int c=0;c<NCH;c++){
        if (c+1 < NCH){
            const uint16_t* src = g_bt + ((size_t)l*WN + (c+1)*64)*KG;
            uint32_t db = sbase + OFF_B + ((c+1)&1)*16384;
#pragma unroll
            for (int i=0;i<8;i++){
                int cid = tid + i*128;
                int n = cid>>4, j = cid&15;
                cpa16(db + ((n*16 + (j ^ (n&7)))<<4), src + (size_t)n*KG + j*8);
            }
            cp_commit();
        }

        float a8[24];
        float a9[8];
        if (c >= 8){
#pragma unroll
            for (int i=0;i<24;i++) a8[i]=0.f;
#pragma unroll
            for (int i=0;i<8;i++)  a9[i]=0.f;
        }
        if (c == 0){
#pragma unroll
            for (int i=0;i<16;i++) m0[i]=0.f;
        }
        if (c == 4){
#pragma unroll
            for (int i=0;i<16;i++) m1[i]=0.f;
        }

        uint32_t bb = sbase + OFF_B + (c&1)*16384;
#pragma unroll
        for (int p=0;p<2;p++){
            /* GEMM half-pass: nf = p*4+nf', both M-tiles share B-frags */
            float acc0[16], acc1[16];
#pragma unroll
            for (int i=0;i<16;i++){ acc0[i]=0.f; acc1[i]=0.f; }
#pragma unroll
            for (int q4=0;q4<4;q4++){
#pragma unroll
                for (int nf=0;nf<4;nf++){
                    int nfg = p*4 + nf;
                    uint32_t bm[4];
                    ldsm4(bm, bb + (((nfg*8 + rowin)*16 + ((q4*4+mi) ^ rowin)) << 4));
                    mma16816(acc0 + nf*4, A0 + (2*q4)*4, bm[0], bm[1]);
                    mma16816(acc1 + nf*4, A1 + (2*q4)*4, bm[0], bm[1]);
                    if (q4 < 3){
                        mma16816(acc0 + nf*4, A0 + (2*q4+1)*4, bm[2], bm[3]);
                        mma16816(acc1 + nf*4, A1 + (2*q4+1)*4, bm[2], bm[3]);
                    }
                }
            }
            /* consume pass */
            if (c < 4){
#pragma unroll
                for (int nf=0;nf<4;nf++){
                    int u = c*4 + p*2 + (nf>>1);
                    int sl = (nf&1)*2;
                    float s0 = Fp0[u], s1 = Fp1[u], s2 = Fp2[u], s3 = Fp3[u];
                    m0[sl+0]  += acc0[nf*4+0]*s0;  m0[sl+1]  += acc0[nf*4+1]*s0;
                    m0[4+sl]  += acc0[nf*4+2]*s1;  m0[5+sl]  += acc0[nf*4+3]*s1;
                    m0[8+sl]  += acc1[nf*4+0]*s2;  m0[9+sl]  += acc1[nf*4+1]*s2;
                    m0[12+sl] += acc1[nf*4+2]*s3;  m0[13+sl] += acc1[nf*4+3]*s3;
                }
            } else if (c < 8){
#pragma unroll
                for (int nf=0;nf<4;nf++){
                    int u = (c-4)*4 + p*2 + (nf>>1);
                    int sl = (nf&1)*2;
                    float s0 = Fp0[u], s1 = Fp1[u], s2 = Fp2[u], s3 = Fp3[u];
                    m1[sl+0]  += acc0[nf*4+0]*s0;  m1[sl+1]  += acc0[nf*4+1]*s0;
                    m1[4+sl]  += acc0[nf*4+2]*s1;  m1[5+sl]  += acc0[nf*4+3]*s1;
                    m1[8+sl]  += acc1[nf*4+0]*s2;  m1[9+sl]  += acc1[nf*4+1]*s2;
                    m1[12+sl] += acc1[nf*4+2]*s3;  m1[13+sl] += acc1[nf*4+3]*s3;
                }
            } else if (c == 9){
#pragma unroll
                for (int nf=0;nf<4;nf++){
                    int u = p*4 + nf;
                    a9[0] += acc0[nf*4+0]*Fp0[40+u];  a9[1] += acc0[nf*4+1]*Fp0[40+u];
                    a9[2] += acc0[nf*4+2]*Fp1[40+u];  a9[3] += acc0[nf*4+3]*Fp1[40+u];
                    a9[4] += acc1[nf*4+0]*Fp2[40+u];  a9[5] += acc1[nf*4+1]*Fp2[40+u];
                    a9[6] += acc1[nf*4+2]*Fp3[40+u];  a9[7] += acc1[nf*4+3]*Fp3[40+u];
                }
            } else {  /* c==8 or c==10 */
                int fb = (c==8) ? 16 : 48;
#pragma unroll
                for (int nf=0;nf<4;nf++){
                    int u = p*4 + nf;
#pragma unroll
                    for (int d=0;d<3;d++){
                        a8[0+d]  += acc0[nf*4+0]*Fp0[fb+u*3+d];
                        a8[3+d]  += acc0[nf*4+1]*Fp0[fb+u*3+d];
                        a8[6+d]  += acc0[nf*4+2]*Fp1[fb+u*3+d];
                        a8[9+d]  += acc0[nf*4+3]*Fp1[fb+u*3+d];
                        a8[12+d] += acc1[nf*4+0]*Fp2[fb+u*3+d];
                        a8[15+d] += acc1[nf*4+1]*Fp2[fb+u*3+d];
                        a8[18+d] += acc1[nf*4+2]*Fp3[fb+u*3+d];
                        a8[21+d] += acc1[nf*4+3]*Fp3[fb+u*3+d];
                    }
                }
            }
        }

        /* flushes */
        if (c == 3){
            red2(&g_aggs[cn0*24 + tq],     m0[0]*C_SC,  m0[1]*C_SC);
            red2(&g_aggs[cn0*24 + 8 + tq], m0[2]*C_SC,  m0[3]*C_SC);
            red2(&g_aggs[cn1*24 + tq],     m0[4]*C_SC,  m0[5]*C_SC);
            red2(&g_aggs[cn1*24 + 8 + tq], m0[6]*C_SC,  m0[7]*C_SC);
            red2(&g_aggs[cn2*24 + tq],     m0[8]*C_SC,  m0[9]*C_SC);
            red2(&g_aggs[cn2*24 + 8 + tq], m0[10]*C_SC, m0[11]*C_SC);
            red2(&g_aggs[cn3*24 + tq],     m0[12]*C_SC, m0[13]*C_SC);
            red2(&g_aggs[cn3*24 + 8 + tq], m0[14]*C_SC, m0[15]*C_SC);
        } else if (c == 7){
            const float* Fs[4] = {Fp0, Fp1, Fp2, Fp3};
            int cns[4] = {cn0, cn1, cn2, cn3};
#pragma unroll
            for (int E=0;E<4;E++){
#pragma unroll
                for (int s=0;s<4;s++){
                    int t = (s>>1)*8 + tq + (s&1);
                    float f = m1[E*4+s]*C_SC;
                    red4(&g_aggv[cns[E]*128 + t*4], f*Fs[E][72], f*Fs[E][73], f*Fs[E][74]);
                }
            }
        } else if (c == 8){
            int cns[4] = {cn0, cn1, cn2, cn3};
#pragma unroll
            for (int E=0;E<4;E++){
                red4(&g_aggv[cns[E]*128 + (16+tq)*4],   a8[E*6+0]*C_V0, a8[E*6+1]*C_V0, a8[E*6+2]*C_V0);
                red4(&g_aggv[cns[E]*128 + (16+tq+1)*4], a8[E*6+3]*C_V0, a8[E*6+4]*C_V0, a8[E*6+5]*C_V0);
            }
        } else if (c == 9){
            red2(&g_aggs[cn0*24 + 16 + tq], a9[0]*C_CG, a9[1]*C_CG);
            red2(&g_aggs[cn1*24 + 16 + tq], a9[2]*C_CG, a9[3]*C_CG);
            red2(&g_aggs[cn2*24 + 16 + tq], a9[4]*C_CG, a9[5]*C_CG);
            red2(&g_aggs[cn3*24 + 16 + tq], a9[6]*C_CG, a9[7]*C_CG);
        } else if (c == 10){
            int cns[4] = {cn0, cn1, cn2, cn3};
#pragma unroll
            for (int E=0;E<4;E++){
                red4(&g_aggv[cns[E]*128 + (24+tq)*4],   a8[E*6+0]*C_CG, a8[E*6+1]*C_CG, a8[E*6+2]*C_CG);
                red4(&g_aggv[cns[E]*128 + (24+tq+1)*4], a8[E*6+3]*C_CG, a8[E*6+4]*C_CG, a8[E*6+5]*C_CG);
            }
        }

        cp_wait0();
        __syncthreads();
    }
}

/* ---------------- node updates (zero folded in) ---------------- */
__global__ void upd_s(int l, const float* __restrict__ lws){
    int idx = blockIdx.x*256 + threadIdx.x;
    int n = idx>>4, t = idx&15;
    float a = 0.f;
#pragma unroll
    for (int u=0;u<24;u++) a += g_aggs[n*24+u]*lws[l*384+u*16+t];
    __syncthreads();
    g_s[idx] += a*I24;
    int base = (blockIdx.x<<4)*24;
    for (int i=threadIdx.x;i<384;i+=256) g_aggs[base+i] = 0.f;
}
__global__ void upd_v(int l, const float* __restrict__ lwv){
    int idx = blockIdx.x*256 + threadIdx.x;
    bool act = idx < NN*8;
    int n = act ? (idx>>3) : 0, w = idx&7;
    float ax=0.f, ay=0.f, az=0.f;
    if (act){
#pragma unroll
        for (int u=0;u<32;u++){
            float lw = lwv[l*256+u*8+w];
            ax += g_aggv[n*128+u*4+0]*lw;
            ay += g_aggv[n*128+u*4+1]*lw;
            az += g_aggv[n*128+u*4+2]*lw;
        }
    }
    __syncthreads();
    if (act){
        g_v[n*24+w*3+0] += ax*I32;
        g_v[n*24+w*3+1] += ay*I32;
        g_v[n*24+w*3+2] += az*I32;
    }
    int base = blockIdx.x*32*128;
    for (int i=threadIdx.x;i<4096;i+=256){
        int gidx = base+i;
        if (gidx < NN*128) g_aggv[gidx] = 0.f;
    }
}

/* ---------------- output ---------------- */
__global__ void out_kernel(const float* __restrict__ ow, float* __restrict__ out){
    int idx = blockIdx.x*256 + threadIdx.x;
    if (idx >= NN*8) return;
    int n = idx>>3, t = idx&7;
    float a = 0.f;
#pragma unroll
    for (int k=0;k<16;k++) a += g_s[n*16+k]*ow[k*8+t];
    out[idx] = a*I16;
}

/* ---------------- launch ---------------- */
extern "C" void kernel_launch(void* const* d_in, const int* in_sizes, int n_in,
                              void* d_out, int out_size){
    const float *x=0, *pos=0, *embed_w=0, *radial_w=0, *radial_b=0;
    const float *fc_w=0, *fc_b=0, *lin_ws=0, *lin_wv=0, *out_w=0;
    const int *ei=0;
    for (int i=0;i<n_in;i++){
        switch (in_sizes[i]){
            case 80000:  x=(const float*)d_in[i]; break;
            case 30000:  pos=(const float*)d_in[i]; break;
            case 4000:   radial_w=(const float*)d_in[i]; break;
            case 400:    radial_b=(const float*)d_in[i]; break;
            case 281600: fc_w=(const float*)d_in[i]; break;
            case 2816:   fc_b=(const float*)d_in[i]; break;
            case 1536:   lin_ws=(const float*)d_in[i]; break;
            case 1024:   lin_wv=(const float*)d_in[i]; break;
            case 320000: ei=(const int*)d_in[i]; break;
            case 128:
                if (!embed_w) embed_w=(const float*)d_in[i];
                else          out_w=(const float*)d_in[i];
                break;
        }
    }
    const int* row = ei;
    const int* col = ei + NE;
    float* out = (float*)d_out;

    cudaFuncSetAttribute(msg_kernel, cudaFuncAttributeMaxDynamicSharedMemorySize, SM_TOT);

    conv_fcw<<<(4*WN*KG + 255)/256, 256>>>(fc_w, fc_b);
    conv_rwt<<<(4*RN*12 + 255)/256, 256>>>(radial_w, radial_b);
    geom_kernel<<<(NE+255)/256, 256>>>(pos, row, col);
    init_kernel<<<(NN*16+255)/256, 256>>>(x, embed_w);

    for (int l=0;l<4;l++){
        msg_kernel<<<NE/EB, 128, SM_TOT>>>(l, row, col);
        upd_s<<<NN*16/256, 256>>>(l, lin_ws);
        upd_v<<<(NN*8+255)/256, 256>>>(l, lin_wv);
    }
    out_kernel<<<(NN*8+255)/256, 256>>>(out_w, out);
}

// round 13
// speedup vs baseline: 1.2321x; 1.0287x over previous
#include <cuda_runtime.h>
#include <cuda_fp16.h>
#include <math.h>
#include <stdint.h>

#define NN 10000
#define NE 160000
#define NB 10
#define RN 100
#define WN 704
#define NCH 11
#define EB 128
#define KG 128
#define HS 130        /* hh row stride in halves (conflict-free) */

#define SQ3    1.7320508075688772f
#define ISQ3   0.5773502691896258f
#define SQ75   2.7386127875258306f
#define C_SC   0.25f
#define C_V0   0.35355339059327373f
#define C_CG   0.20412414523193152f
#define I24    0.20412414523193152f
#define I32    0.17677669529663687f
#define I8     0.35355339059327373f
#define I16    0.25f
#define THIRD  0.3333333333333333f

__device__ float g_rbf[NE*NB];
__device__ float g_sh1[NE*3];
__device__ float g_s[NN*16];
__device__ float g_v[NN*24];
__device__ float g_aggs[NN*24];
__device__ float g_aggv[NN*128];     /* [N][32][4] for float4 atomics */
__device__ uint16_t g_bt[4*WN*KG];   /* fc_w^T fp16, [l][n][k] padded */
__device__ float g_rwT[4*RN*12];     /* radial w transposed: [l][r][10 w + bias + pad] */

/* ---- smem layout (bytes) ----
   UNION @0: hh (128*130*2 = 33280) overlaid with feat (128*77*4 = 39424)
   COL   @39424 (512)
   B     @39936 (2 x 16384)                                              */
#define OFF_U    0
#define OFF_COL  39424
#define OFF_B    39936
#define SM_TOT   72704
#define FST 77

__device__ __forceinline__ uint32_t smem_u32(const void* p){
    uint32_t a; asm("{ .reg .u64 t; cvta.to.shared.u64 t, %1; cvt.u32.u64 %0, t; }":"=r"(a):"l"(p)); return a;
}
__device__ __forceinline__ void cpa16(uint32_t dst, const void* src){
    asm volatile("cp.async.ca.shared.global [%0], [%1], 16;"::"r"(dst),"l"(src):"memory");
}
__device__ __forceinline__ void cp_commit(){ asm volatile("cp.async.commit_group;":::"memory"); }
__device__ __forceinline__ void cp_wait0(){ asm volatile("cp.async.wait_group 0;":::"memory"); }
__device__ __forceinline__ void ldsm4(uint32_t* r, uint32_t a){
    asm volatile("ldmatrix.sync.aligned.m8n8.x4.shared.b16 {%0,%1,%2,%3}, [%4];"
        :"=r"(r[0]),"=r"(r[1]),"=r"(r[2]),"=r"(r[3]):"r"(a));
}
__device__ __forceinline__ void mma16816(float* d, const uint32_t* a, uint32_t b0, uint32_t b1){
    asm volatile("mma.sync.aligned.m16n8k16.row.col.f32.f16.f16.f32 "
        "{%0,%1,%2,%3}, {%4,%5,%6,%7}, {%8,%9}, {%0,%1,%2,%3};"
        : "+f"(d[0]),"+f"(d[1]),"+f"(d[2]),"+f"(d[3])
        : "r"(a[0]),"r"(a[1]),"r"(a[2]),"r"(a[3]),"r"(b0),"r"(b1));
}
__device__ __forceinline__ void red2(float* p, float a, float b){
    atomicAdd((float2*)p, make_float2(a,b));
}
__device__ __forceinline__ void red4(float* p, float a, float b, float c){
    atomicAdd((float4*)p, make_float4(a,b,c,0.f));
}

/* ---------------- geometry ---------------- */
__global__ void geom_kernel(const float* __restrict__ pos, const int* __restrict__ row, const int* __restrict__ col){
    int e = blockIdx.x*256 + threadIdx.x;
    if (e >= NE) return;
    int r = row[e], c = col[e];
    float vx = pos[3*r]-pos[3*c], vy = pos[3*r+1]-pos[3*c+1], vz = pos[3*r+2]-pos[3*c+2];
    float len = sqrtf(vx*vx+vy*vy+vz*vz+1e-12f);
    float inv = 1.0f/len;
    g_sh1[3*e]=SQ3*vx*inv; g_sh1[3*e+1]=SQ3*vy*inv; g_sh1[3*e+2]=SQ3*vz*inv;
    const float step = 10.0f/9.0f;
#pragma unroll
    for (int k=0;k<NB;k++){ float d = len - (float)k*step; g_rbf[e*NB+k] = expf(-0.405f*d*d); }
}

/* ---------------- init ---------------- */
__global__ void init_kernel(const float* __restrict__ x, const float* __restrict__ ew){
    int idx = blockIdx.x*blockDim.x + threadIdx.x;
    int nt = gridDim.x*blockDim.x;
    if (idx < NN*16){
        int n = idx>>4, t = idx&15;
        float a = 0.f;
#pragma unroll
        for (int k=0;k<8;k++) a += x[n*8+k]*ew[k*16+t];
        g_s[idx] = a*I8;
    }
    for (int i=idx;i<NN*24;i+=nt){ g_v[i]=0.f; g_aggs[i]=0.f; }
    for (int i=idx;i<NN*128;i+=nt) g_aggv[i]=0.f;
}

/* ---------------- one-time conversions ---------------- */
__global__ void conv_fcw(const float* __restrict__ fcw, const float* __restrict__ fcb){
    int idx = blockIdx.x*256 + threadIdx.x;
    if (idx >= 4*WN*KG) return;
    int k = idx & (KG-1);
    int n = (idx >> 7) % WN;
    int l = idx / (WN*KG);
    float v = 0.f;
    if (k < 100)       v = fcw[(size_t)(l*RN + k)*WN + n];
    else if (k == 100) v = fcb[l*WN + n];
    __half h = __float2half_rn(v);
    g_bt[idx] = *(uint16_t*)&h;
}
__global__ void conv_rwt(const float* __restrict__ rw, const float* __restrict__ rb){
    int idx = blockIdx.x*256 + threadIdx.x;
    if (idx >= 4*RN*12) return;
    int j = idx % 12;
    int r = (idx/12) % RN;
    int l = idx / (RN*12);
    float v = 0.f;
    if (j < 10)       v = rw[l*1000 + j*100 + r];
    else if (j == 10) v = rb[l*100 + r];
    g_rwT[idx] = v;
}

/* ---------------- fused HMMA message kernel: 4 warps, Tm=32 ---------------- */
__global__ void __launch_bounds__(128, 3)
msg_kernel(int l, const int* __restrict__ row, const int* __restrict__ col){
    extern __shared__ char smem[];
    uint32_t sbase = smem_u32(smem);
    int tid = threadIdx.x;
    int wid = tid>>5, lane = tid&31;
    int g = lane>>2, tig = lane&3;
    int mi = lane>>3, rowin = lane&7;
    int tq = tig*2;
    int e0 = blockIdx.x*EB;

    uint16_t* hh = (uint16_t*)(smem + OFF_U);
    float*    featf = (float*)(smem + OFF_U);
    int*      colsm = (int*)(smem + OFF_COL);

    /* stage B chunk 0 (1024 x 16B, 128 threads) */
    {
        const uint16_t* src = g_bt + (size_t)l*WN*KG;
#pragma unroll
        for (int i=0;i<8;i++){
            int cid = tid + i*128;
            int n = cid>>4, j = cid&15;
            cpa16(sbase + OFF_B + ((n*16 + (j ^ (n&7)))<<4), src + (size_t)n*KG + j*8);
        }
        cp_commit();
    }

    /* h compute: thread = edge, broadcast float4 LDG weights */
    {
        int eg = e0 + tid;
        float rbf[NB];
        const float2* rb2 = (const float2*)(g_rbf + (size_t)eg*NB);
#pragma unroll
        for (int i=0;i<5;i++){ float2 v = rb2[i]; rbf[i*2]=v.x; rbf[i*2+1]=v.y; }
        const float4* wt = (const float4*)(g_rwT + l*RN*12);
        uint16_t* hrow = hh + tid*HS;
#pragma unroll 4
        for (int r=0;r<RN;r++){
            float4 c0 = wt[r*3], c1 = wt[r*3+1], c2 = wt[r*3+2];
            float a = c2.z
                + rbf[0]*c0.x + rbf[1]*c0.y + rbf[2]*c0.z + rbf[3]*c0.w
                + rbf[4]*c1.x + rbf[5]*c1.y + rbf[6]*c1.z + rbf[7]*c1.w
                + rbf[8]*c2.x + rbf[9]*c2.y;
            a = fmaxf(a, 0.f);
            __half hv = __float2half_rn(a);
            hrow[r] = *(uint16_t*)&hv;
        }
        hrow[100] = 0x3C00;                 /* bias row: A = 1.0 */
#pragma unroll
        for (int r=101;r<112;r++) hrow[r] = 0;
    }
    __syncthreads();

    /* A fragment preload: warp strip = 32 edges (rows r0,+8 and r0+16,+24) */
    uint32_t A0[28], A1[28];
    int r0 = wid*32 + g;
    {
#pragma unroll
        for (int ks=0;ks<7;ks++){
            int k0 = ks*16 + tq;
            A0[ks*4+0] = *(uint32_t*)&hh[r0*HS + k0];
            A0[ks*4+1] = *(uint32_t*)&hh[(r0+8)*HS + k0];
            A0[ks*4+2] = *(uint32_t*)&hh[r0*HS + k0+8];
            A0[ks*4+3] = *(uint32_t*)&hh[(r0+8)*HS + k0+8];
            A1[ks*4+0] = *(uint32_t*)&hh[(r0+16)*HS + k0];
            A1[ks*4+1] = *(uint32_t*)&hh[(r0+24)*HS + k0];
            A1[ks*4+2] = *(uint32_t*)&hh[(r0+16)*HS + k0+8];
            A1[ks*4+3] = *(uint32_t*)&hh[(r0+24)*HS + k0+8];
        }
    }
    __syncthreads();   /* hh dead; feat overlays */

    /* features + col: thread = edge */
    {
        int e = tid, eg = e0 + e;
        int rr = row[eg];
        colsm[e] = col[eg];
        float* F = featf + e*FST;
#pragma unroll
        for (int t=0;t<16;t++) F[t] = g_s[rr*16+t];
#pragma unroll
        for (int i=0;i<24;i++) F[16+i] = g_v[rr*24+i];
        float s1x = g_sh1[eg*3], s1y = g_sh1[eg*3+1], s1z = g_sh1[eg*3+2];
        F[72]=s1x; F[73]=s1y; F[74]=s1z;
        float ux=s1x*ISQ3, uy=s1y*ISQ3, uz=s1z*ISQ3;
#pragma unroll
        for (int u=0;u<8;u++){
            float vx=F[16+u*3], vy=F[17+u*3], vz=F[18+u*3];
            float dot = ux*vx+uy*vy+uz*vz;
            F[40+u] = SQ3*dot;
            F[48+u*3] = SQ75*(dot*ux - vx*THIRD);
            F[49+u*3] = SQ75*(dot*uy - vy*THIRD);
            F[50+u*3] = SQ75*(dot*uz - vz*THIRD);
        }
    }
    cp_wait0();
    __syncthreads();

    const float* Fp0 = featf + r0*FST;
    const float* Fp1 = featf + (r0+8)*FST;
    const float* Fp2 = featf + (r0+16)*FST;
    const float* Fp3 = featf + (r0+24)*FST;
    int cn0 = colsm[r0], cn1 = colsm[r0+8], cn2 = colsm[r0+16], cn3 = colsm[r0+24];
    float m0[16], m1[16];

#pragma unroll
    for (int c=0;c<NCH;c++){
        if (c+1 < NCH){
            const uint16_t* src = g_bt + ((size_t)l*WN + (c+1)*64)*KG;
            uint32_t db = sbase + OFF_B + ((c+1)&1)*16384;
#pragma unroll
            for (int i=0;i<8;i++){
                int cid = tid + i*128;
                int n = cid>>4, j = cid&15;
                cpa16(db + ((n*16 + (j ^ (n&7)))<<4), src + (size_t)n*KG + j*8);
            }
            cp_commit();
        }

        float a8[24];
        float a9[8];
        if (c >= 8){
#pragma unroll
            for (int i=0;i<24;i++) a8[i]=0.f;
#pragma unroll
            for (int i=0;i<8;i++)  a9[i]=0.f;
        }
        if (c == 0){
#pragma unroll
            for (int i=0;i<16;i++) m0[i]=0.f;
        }
        if (c == 4){
#pragma unroll
            for (int i=0;i<16;i++) m1[i]=0.f;
        }

        uint32_t bb = sbase + OFF_B + (c&1)*16384;
#pragma unroll
        for (int p=0;p<2;p++){
            /* GEMM half-pass: nf = p*4+nf', both M-tiles share B-frags */
            float acc0[16], acc1[16];
#pragma unroll
            for (int i=0;i<16;i++){ acc0[i]=0.f; acc1[i]=0.f; }
#pragma unroll
            for (int q4=0;q4<4;q4++){
#pragma unroll
                for (int nf=0;nf<4;nf++){
                    int nfg = p*4 + nf;
                    uint32_t bm[4];
                    ldsm4(bm, bb + (((nfg*8 + rowin)*16 + ((q4*4+mi) ^ rowin)) << 4));
                    mma16816(acc0 + nf*4, A0 + (2*q4)*4, bm[0], bm[1]);
                    mma16816(acc1 + nf*4, A1 + (2*q4)*4, bm[0], bm[1]);
                    if (q4 < 3){
                        mma16816(acc0 + nf*4, A0 + (2*q4+1)*4, bm[2], bm[3]);
                        mma16816(acc1 + nf*4, A1 + (2*q4+1)*4, bm[2], bm[3]);
                    }
                }
            }
            /* consume pass */
            if (c < 4){
#pragma unroll
                for (int nf=0;nf<4;nf++){
                    int u = c*4 + p*2 + (nf>>1);
                    int sl = (nf&1)*2;
                    float s0 = Fp0[u], s1 = Fp1[u], s2 = Fp2[u], s3 = Fp3[u];
                    m0[sl+0]  += acc0[nf*4+0]*s0;  m0[sl+1]  += acc0[nf*4+1]*s0;
                    m0[4+sl]  += acc0[nf*4+2]*s1;  m0[5+sl]  += acc0[nf*4+3]*s1;
                    m0[8+sl]  += acc1[nf*4+0]*s2;  m0[9+sl]  += acc1[nf*4+1]*s2;
                    m0[12+sl] += acc1[nf*4+2]*s3;  m0[13+sl] += acc1[nf*4+3]*s3;
                }
            } else if (c < 8){
#pragma unroll
                for (int nf=0;nf<4;nf++){
                    int u = (c-4)*4 + p*2 + (nf>>1);
                    int sl = (nf&1)*2;
                    float s0 = Fp0[u], s1 = Fp1[u], s2 = Fp2[u], s3 = Fp3[u];
                    m1[sl+0]  += acc0[nf*4+0]*s0;  m1[sl+1]  += acc0[nf*4+1]*s0;
                    m1[4+sl]  += acc0[nf*4+2]*s1;  m1[5+sl]  += acc0[nf*4+3]*s1;
                    m1[8+sl]  += acc1[nf*4+0]*s2;  m1[9+sl]  += acc1[nf*4+1]*s2;
                    m1[12+sl] += acc1[nf*4+2]*s3;  m1[13+sl] += acc1[nf*4+3]*s3;
                }
            } else if (c == 9){
#pragma unroll
                for (int nf=0;nf<4;nf++){
                    int u = p*4 + nf;
                    a9[0] += acc0[nf*4+0]*Fp0[40+u];  a9[1] += acc0[nf*4+1]*Fp0[40+u];
                    a9[2] += acc0[nf*4+2]*Fp1[40+u];  a9[3] += acc0[nf*4+3]*Fp1[40+u];
                    a9[4] += acc1[nf*4+0]*Fp2[40+u];  a9[5] += acc1[nf*4+1]*Fp2[40+u];
                    a9[6] += acc1[nf*4+2]*Fp3[40+u];  a9[7] += acc1[nf*4+3]*Fp3[40+u];
                }
            } else {  /* c==8 or c==10 */
                int fb = (c==8) ? 16 : 48;
#pragma unroll
                for (int nf=0;nf<4;nf++){
                    int u = p*4 + nf;
#pragma unroll
                    for (int d=0;d<3;d++){
                        a8[0+d]  += acc0[nf*4+0]*Fp0[fb+u*3+d];
                        a8[3+d]  += acc0[nf*4+1]*Fp0[fb+u*3+d];
                        a8[6+d]  += acc0[nf*4+2]*Fp1[fb+u*3+d];
                        a8[9+d]  += acc0[nf*4+3]*Fp1[fb+u*3+d];
                        a8[12+d] += acc1[nf*4+0]*Fp2[fb+u*3+d];
                        a8[15+d] += acc1[nf*4+1]*Fp2[fb+u*3+d];
                        a8[18+d] += acc1[nf*4+2]*Fp3[fb+u*3+d];
                        a8[21+d] += acc1[nf*4+3]*Fp3[fb+u*3+d];
                    }
                }
            }
        }

        /* flushes */
        if (c == 3){
            red2(&g_aggs[cn0*24 + tq],     m0[0]*C_SC,  m0[1]*C_SC);
            red2(&g_aggs[cn0*24 + 8 + tq], m0[2]*C_SC,  m0[3]*C_SC);
            red2(&g_aggs[cn1*24 + tq],     m0[4]*C_SC,  m0[5]*C_SC);
            red2(&g_aggs[cn1*24 + 8 + tq], m0[6]*C_SC,  m0[7]*C_SC);
            red2(&g_aggs[cn2*24 + tq],     m0[8]*C_SC,  m0[9]*C_SC);
            red2(&g_aggs[cn2*24 + 8 + tq], m0[10]*C_SC, m0[11]*C_SC);
            red2(&g_aggs[cn3*24 + tq],     m0[12]*C_SC, m0[13]*C_SC);
            red2(&g_aggs[cn3*24 + 8 + tq], m0[14]*C_SC, m0[15]*C_SC);
        } else if (c == 7){
            const float* Fs[4] = {Fp0, Fp1, Fp2, Fp3};
            int cns[4] = {cn0, cn1, cn2, cn3};
#pragma unroll
            for (int E=0;E<4;E++){
#pragma unroll
                for (int s=0;s<4;s++){
                    int t = (s>>1)*8 + tq + (s&1);
                    float f = m1[E*4+s]*C_SC;
                    red4(&g_aggv[cns[E]*128 + t*4], f*Fs[E][72], f*Fs[E][73], f*Fs[E][74]);
                }
            }
        } else if (c == 8){
            int cns[4] = {cn0, cn1, cn2, cn3};
#pragma unroll
            for (int E=0;E<4;E++){
                red4(&g_aggv[cns[E]*128 + (16+tq)*4],   a8[E*6+0]*C_V0, a8[E*6+1]*C_V0, a8[E*6+2]*C_V0);
                red4(&g_aggv[cns[E]*128 + (16+tq+1)*4], a8[E*6+3]*C_V0, a8[E*6+4]*C_V0, a8[E*6+5]*C_V0);
            }
        } else if (c == 9){
            red2(&g_aggs[cn0*24 + 16 + tq], a9[0]*C_CG, a9[1]*C_CG);
            red2(&g_aggs[cn1*24 + 16 + tq], a9[2]*C_CG, a9[3]*C_CG);
            red2(&g_aggs[cn2*24 + 16 + tq], a9[4]*C_CG, a9[5]*C_CG);
            red2(&g_aggs[cn3*24 + 16 + tq], a9[6]*C_CG, a9[7]*C_CG);
        } else if (c == 10){
            int cns[4] = {cn0, cn1, cn2, cn3};
#pragma unroll
            for (int E=0;E<4;E++){
                red4(&g_aggv[cns[E]*128 + (24+tq)*4],   a8[E*6+0]*C_CG, a8[E*6+1]*C_CG, a8[E*6+2]*C_CG);
                red4(&g_aggv[cns[E]*128 + (24+tq+1)*4], a8[E*6+3]*C_CG, a8[E*6+4]*C_CG, a8[E*6+5]*C_CG);
            }
        }

        cp_wait0();
        __syncthreads();
    }
}

/* ---------------- fused node update: blocks 0..624 = s, 625..937 = v ---------------- */
#define SBLK 625
__global__ void upd_kernel(int l, const float* __restrict__ lws, const float* __restrict__ lwv){
    int tid = threadIdx.x;
    if (blockIdx.x < SBLK){
        /* s-update: 16 nodes per block */
        int idx = blockIdx.x*256 + tid;
        int n = idx>>4, t = idx&15;
        float a = 0.f;
#pragma unroll
        for (int u=0;u<24;u++) a += g_aggs[n*24+u]*lws[l*384+u*16+t];
        __syncthreads();
        g_s[idx] += a*I24;
        float4* z4 = (float4*)(g_aggs + (size_t)blockIdx.x*384);
        if (tid < 96) z4[tid] = make_float4(0.f,0.f,0.f,0.f);
    } else {
        /* v-update: 32 nodes per block */
        int vb = blockIdx.x - SBLK;
        int idx = vb*256 + tid;
        bool act = idx < NN*8;
        int n = act ? (idx>>3) : 0, w = idx&7;
        float ax=0.f, ay=0.f, az=0.f;
        if (act){
            const float4* av = (const float4*)(g_aggv + (size_t)n*128);
#pragma unroll
            for (int u=0;u<32;u++){
                float lw = lwv[l*256+u*8+w];
                float4 a4 = av[u];
                ax += a4.x*lw; ay += a4.y*lw; az += a4.z*lw;
            }
        }
        __syncthreads();
        if (act){
            g_v[n*24+w*3+0] += ax*I32;
            g_v[n*24+w*3+1] += ay*I32;
            g_v[n*24+w*3+2] += az*I32;
        }
        size_t base4 = (size_t)vb*1024;          /* 32 nodes * 128 floats = 1024 float4 */
        float4* z4 = (float4*)g_aggv;
        float4 z = make_float4(0.f,0.f,0.f,0.f);
#pragma unroll
        for (int i=0;i<4;i++){
            size_t gi = base4 + tid + i*256;
            if (gi < (size_t)NN*32) z4[gi] = z;
        }
    }
}

/* ---------------- output ---------------- */
__global__ void out_kernel(const float* __restrict__ ow, float* __restrict__ out){
    int idx = blockIdx.x*256 + threadIdx.x;
    if (idx >= NN*8) return;
    int n = idx>>3, t = idx&7;
    float a = 0.f;
#pragma unroll
    for (int k=0;k<16;k++) a += g_s[n*16+k]*ow[k*8+t];
    out[idx] = a*I16;
}

/* ---------------- launch ---------------- */
extern "C" void kernel_launch(void* const* d_in, const int* in_sizes, int n_in,
                              void* d_out, int out_size){
    const float *x=0, *pos=0, *embed_w=0, *radial_w=0, *radial_b=0;
    const float *fc_w=0, *fc_b=0, *lin_ws=0, *lin_wv=0, *out_w=0;
    const int *ei=0;
    for (int i=0;i<n_in;i++){
        switch (in_sizes[i]){
            case 80000:  x=(const float*)d_in[i]; break;
            case 30000:  pos=(const float*)d_in[i]; break;
            case 4000:   radial_w=(const float*)d_in[i]; break;
            case 400:    radial_b=(const float*)d_in[i]; break;
            case 281600: fc_w=(const float*)d_in[i]; break;
            case 2816:   fc_b=(const float*)d_in[i]; break;
            case 1536:   lin_ws=(const float*)d_in[i]; break;
            case 1024:   lin_wv=(const float*)d_in[i]; break;
            case 320000: ei=(const int*)d_in[i]; break;
            case 128:
                if (!embed_w) embed_w=(const float*)d_in[i];
                else          out_w=(const float*)d_in[i];
                break;
        }
    }
    const int* row = ei;
    const int* col = ei + NE;
    float* out = (float*)d_out;

    cudaFuncSetAttribute(msg_kernel, cudaFuncAttributeMaxDynamicSharedMemorySize, SM_TOT);

    conv_fcw<<<(4*WN*KG + 255)/256, 256>>>(fc_w, fc_b);
    conv_rwt<<<(4*RN*12 + 255)/256, 256>>>(radial_w, radial_b);
    geom_kernel<<<(NE+255)/256, 256>>>(pos, row, col);
    init_kernel<<<(NN*16+255)/256, 256>>>(x, embed_w);

    for (int l=0;l<4;l++){
        msg_kernel<<<NE/EB, 128, SM_TOT>>>(l, row, col);
        upd_kernel<<<SBLK + (NN*8 + 255)/256, 256>>>(l, lin_ws, lin_wv);
    }
    out_kernel<<<(NN*8+255)/256, 256>>>(out_w, out);
}